// round 14
// baseline (speedup 1.0000x reference)
#include <cuda_runtime.h>
#include <cuda_fp16.h>
#include <cstdint>
#include <cstddef>

// ----------------------------------------------------------------------------
// LoRALinear: out = x @ Weff^T + b, Weff = W + 2*(gB@gA + lB@lA)
//   k1 (merged): fp16-round x -> g_Xh AND fold LoRA -> g_Wh, both k-permuted
//       per 16: [k0,k1,k8,k9, k2,k3,k10,k11, k4,k5,k12,k13, k6,k7,k14,k15]
//   k2: mma.sync m16n8k16 f16 GEMM (fp32 accum), BM=128 BN=256 BK=64,
//       4-stage cp.async ring, conflict-free 144B smem row stride.
// ----------------------------------------------------------------------------

#define LORA_SCALE 2.0f
#define MAXM 16384
#define MAXK 1024
#define MAXN 4096

__device__ __half g_Xh[MAXM * MAXK];    // 32 MB scratch (permuted-k fp16)
__device__ __half g_Wh[MAXN * MAXK];    // 8 MB scratch (permuted-k fp16)

// ---- merged prep kernel ----------------------------------------------------
__global__ void prep_kernel(const float4* __restrict__ x, int n16x,
                            const float4* __restrict__ W,
                            const float4* __restrict__ gA,
                            const float*  __restrict__ gB,
                            const float4* __restrict__ lA,
                            const float*  __restrict__ lB,
                            int K16, int R, int n16w) {
    int i = blockIdx.x * blockDim.x + threadIdx.x;
    if (i < n16x) {
        // ---- x path: round + permute ----
        float4 a = x[4 * i + 0];
        float4 b = x[4 * i + 1];
        float4 c = x[4 * i + 2];
        float4 d = x[4 * i + 3];
        __half2 h[8];
        h[0] = __floats2half2_rn(a.x, a.y);
        h[1] = __floats2half2_rn(c.x, c.y);
        h[2] = __floats2half2_rn(a.z, a.w);
        h[3] = __floats2half2_rn(c.z, c.w);
        h[4] = __floats2half2_rn(b.x, b.y);
        h[5] = __floats2half2_rn(d.x, d.y);
        h[6] = __floats2half2_rn(b.z, b.w);
        h[7] = __floats2half2_rn(d.z, d.w);
        uint4* out = reinterpret_cast<uint4*>(g_Xh);
        const uint32_t* u = reinterpret_cast<const uint32_t*>(h);
        out[2 * i]     = make_uint4(u[0], u[1], u[2], u[3]);
        out[2 * i + 1] = make_uint4(u[4], u[5], u[6], u[7]);
        return;
    }
    int j = i - n16x;
    if (j >= n16w) return;
    // ---- Weff path: fold LoRA + round + permute ----
    int o = j / K16;
    int g = j - o * K16;
    int K4 = K16 * 4;
    float4 acc[4];
    #pragma unroll
    for (int q = 0; q < 4; q++) acc[q] = W[4 * j + q];
    for (int r = 0; r < R; r++) {
        float gb = gB[o * R + r] * LORA_SCALE;
        float lb = lB[o * R + r] * LORA_SCALE;
        #pragma unroll
        for (int q = 0; q < 4; q++) {
            float4 ga = gA[r * K4 + 4 * g + q];
            float4 la = lA[r * K4 + 4 * g + q];
            acc[q].x += gb * ga.x + lb * la.x;
            acc[q].y += gb * ga.y + lb * la.y;
            acc[q].z += gb * ga.z + lb * la.z;
            acc[q].w += gb * ga.w + lb * la.w;
        }
    }
    __half2 h[8];
    h[0] = __floats2half2_rn(acc[0].x, acc[0].y);
    h[1] = __floats2half2_rn(acc[2].x, acc[2].y);
    h[2] = __floats2half2_rn(acc[0].z, acc[0].w);
    h[3] = __floats2half2_rn(acc[2].z, acc[2].w);
    h[4] = __floats2half2_rn(acc[1].x, acc[1].y);
    h[5] = __floats2half2_rn(acc[3].x, acc[3].y);
    h[6] = __floats2half2_rn(acc[1].z, acc[1].w);
    h[7] = __floats2half2_rn(acc[3].z, acc[3].w);
    uint4* out = reinterpret_cast<uint4*>(g_Wh);
    const uint32_t* u = reinterpret_cast<const uint32_t*>(h);
    out[2 * j]     = make_uint4(u[0], u[1], u[2], u[3]);
    out[2 * j + 1] = make_uint4(u[4], u[5], u[6], u[7]);
}

// ---- GEMM ------------------------------------------------------------------
#define BM 128
#define BN 256
#define BK 64
#define NS 4
#define SSTH 72                          // halves per row slot (144 B stride)
#define ROWB 144u                        // row stride bytes
#define A_H (BM * SSTH)                  // 9216 halves / stage
#define B_H (BN * SSTH)                  // 18432 halves / stage
#define STAGE_H (A_H + B_H)              // 27648 halves (55296 B)
#define GEMM_SMEM_BYTES (NS * STAGE_H * 2)   // 221184 B

__device__ __forceinline__ void cp16(uint32_t dst, const void* src) {
    asm volatile("cp.async.cg.shared.global [%0], [%1], 16;" :: "r"(dst), "l"(src));
}

__device__ __forceinline__ void mma16(float* c, const uint32_t* a, const uint32_t* b) {
    asm volatile(
        "mma.sync.aligned.m16n8k16.row.col.f32.f16.f16.f32 "
        "{%0,%1,%2,%3}, {%4,%5,%6,%7}, {%8,%9}, {%0,%1,%2,%3};"
        : "+f"(c[0]), "+f"(c[1]), "+f"(c[2]), "+f"(c[3])
        : "r"(a[0]), "r"(a[1]), "r"(a[2]), "r"(a[3]), "r"(b[0]), "r"(b[1]));
}

// issue cp.async group for K-tile kt into slot s (always commits a group)
__device__ __forceinline__ void issue_tile(const __half* Ag, const __half* Bg,
                                           int K, int KT, uint32_t a_base,
                                           int tid, int kt, int s) {
    if (kt < KT) {
        const int r0  = tid >> 3;            // 0..31
        const int ch  = tid & 7;             // 16B chunk within 128B of data
        const int kof = kt * BK + ch * 8;    // halves
        const uint32_t sb = a_base + (uint32_t)(s * STAGE_H) * 2u;
        #pragma unroll
        for (int i = 0; i < 4; i++) {        // A: 128 rows x 144B stride
            int row = r0 + 32 * i;
            cp16(sb + (uint32_t)row * ROWB + (uint32_t)ch * 16u,
                 Ag + (size_t)row * K + kof);
        }
        const uint32_t bb = sb + (uint32_t)A_H * 2u;
        #pragma unroll
        for (int i = 0; i < 8; i++) {        // B: 256 rows x 144B stride
            int row = r0 + 32 * i;
            cp16(bb + (uint32_t)row * ROWB + (uint32_t)ch * 16u,
                 Bg + (size_t)row * K + kof);
        }
    }
    asm volatile("cp.async.commit_group;" ::: "memory");
}

__global__ void __launch_bounds__(256, 1)
gemm_f16_kernel(const float* __restrict__ bias, float* __restrict__ C,
                int M, int N, int K) {
    extern __shared__ __half smem[];
    uint32_t a_base = (uint32_t)__cvta_generic_to_shared(smem);

    const int tid  = threadIdx.x;
    const int lane = tid & 31;
    const int warp = tid >> 5;
    const int wm   = warp & 1;        // 2 warps over M (64 each)
    const int wn   = warp >> 1;       // 4 warps over N (64 each)
    const int bm   = blockIdx.y * BM;
    const int bn   = blockIdx.x * BN;

    const __half* Ag = g_Xh + (size_t)bm * K;
    const __half* Bg = g_Wh + (size_t)bn * K;

    float c[4][8][4];
    #pragma unroll
    for (int mt = 0; mt < 4; mt++)
        #pragma unroll
        for (int nt = 0; nt < 8; nt++)
            #pragma unroll
            for (int r = 0; r < 4; r++)
                c[mt][nt][r] = 0.0f;

    const int KT = K / BK;            // 16

    issue_tile(Ag, Bg, K, KT, a_base, tid, 0, 0);
    issue_tile(Ag, Bg, K, KT, a_base, tid, 1, 1);
    issue_tile(Ag, Bg, K, KT, a_base, tid, 2, 2);

    const int t  = lane & 3;          // threadID in mma group
    const int gr = lane >> 2;         // groupID

    for (int kt = 0; kt < KT; kt++) {
        const int s = kt & (NS - 1);
        asm volatile("cp.async.wait_group %0;" :: "n"(NS - 2) : "memory");
        __syncthreads();
        // refill slot (kt+3)&3 == slot of compute(kt-1), safe after the sync
        issue_tile(Ag, Bg, K, KT, a_base, tid, kt + 3, (kt + 3) & (NS - 1));

        const __half* As = smem + s * STAGE_H;
        const __half* Bs = As + A_H;

        #pragma unroll
        for (int g = 0; g < 4; g++) {             // 4 x (k=16) steps
            const int kp = g * 16 + t * 4;        // halves
            uint32_t afr[4][4];
            uint32_t bfr[8][2];
            const int ar = wm * 64 + gr;
            #pragma unroll
            for (int mt = 0; mt < 4; mt++) {
                uint2 v0 = *reinterpret_cast<const uint2*>(As + (ar + mt * 16) * SSTH + kp);
                uint2 v1 = *reinterpret_cast<const uint2*>(As + (ar + mt * 16 + 8) * SSTH + kp);
                afr[mt][0] = v0.x;
                afr[mt][1] = v1.x;
                afr[mt][2] = v0.y;
                afr[mt][3] = v1.y;
            }
            const int br = wn * 64 + gr;
            #pragma unroll
            for (int nt = 0; nt < 8; nt++) {
                uint2 w = *reinterpret_cast<const uint2*>(Bs + (br + nt * 8) * SSTH + kp);
                bfr[nt][0] = w.x;
                bfr[nt][1] = w.y;
            }
            #pragma unroll
            for (int mt = 0; mt < 4; mt++)
                #pragma unroll
                for (int nt = 0; nt < 8; nt++)
                    mma16(c[mt][nt], afr[mt], bfr[nt]);
        }
    }

    // epilogue: += bias, store float2
    #pragma unroll
    for (int mt = 0; mt < 4; mt++) {
        int row0 = bm + wm * 64 + mt * 16 + gr;
        #pragma unroll
        for (int nt = 0; nt < 8; nt++) {
            int col = bn + wn * 64 + nt * 8 + t * 2;
            float2 bv = *reinterpret_cast<const float2*>(bias + col);
            float2 v0 = { c[mt][nt][0] + bv.x, c[mt][nt][1] + bv.y };
            float2 v1 = { c[mt][nt][2] + bv.x, c[mt][nt][3] + bv.y };
            *reinterpret_cast<float2*>(C + (size_t)row0 * N + col)       = v0;
            *reinterpret_cast<float2*>(C + (size_t)(row0 + 8) * N + col) = v1;
        }
    }
}

// ---- launch ----------------------------------------------------------------
extern "C" void kernel_launch(void* const* d_in, const int* in_sizes, int n_in,
                              void* d_out, int out_size) {
    (void)n_in; (void)out_size;
    const float* x  = (const float*)d_in[0];
    const float* W  = (const float*)d_in[1];
    const float* b  = (const float*)d_in[2];
    const float* gA = (const float*)d_in[3];
    const float* gB = (const float*)d_in[4];
    const float* lA = (const float*)d_in[5];
    const float* lB = (const float*)d_in[6];

    const int N = in_sizes[2];               // 4096
    const int K = in_sizes[1] / N;           // 1024
    const int R = in_sizes[4] / N;           // 8
    const int M = in_sizes[0] / K;           // 16384

    int n16x = (M * K) / 16;                 // x 16-k groups
    int K16  = K / 16;
    int n16w = N * K16;                      // Weff 16-k groups
    int blocks = (n16x + n16w + 255) / 256;
    prep_kernel<<<blocks, 256>>>((const float4*)x, n16x, (const float4*)W,
                                 (const float4*)gA, gB, (const float4*)lA, lB,
                                 K16, R, n16w);

    cudaFuncSetAttribute(gemm_f16_kernel,
                         cudaFuncAttributeMaxDynamicSharedMemorySize, GEMM_SMEM_BYTES);
    dim3 grid(N / BN, M / BM);               // (16, 128)
    gemm_f16_kernel<<<grid, 256, GEMM_SMEM_BYTES>>>(b, (float*)d_out, M, N, K);
}

// round 15
// speedup vs baseline: 1.2725x; 1.2725x over previous
#include <cuda_runtime.h>
#include <cuda_fp16.h>
#include <cstdint>
#include <cstddef>

// ----------------------------------------------------------------------------
// LoRALinear: out = x @ Weff^T + b, Weff = W + 2*(gB@gA + lB@lA)
//   k1 (merged): fold LoRA -> g_Wh (first), fp16-round x -> g_Xh, k-permuted
//       per 16: [k0,k1,k8,k9, k2,k3,k10,k11, k4,k5,k12,k13, k6,k7,k14,k15]
//   k2: mma.sync m16n8k16 f16 GEMM (fp32 accum), BM=128 BN=128 BK=64,
//       NS=2 cp.async, 160B stride (conflict-free), 2 CTAs/SM.
// ----------------------------------------------------------------------------

#define LORA_SCALE 2.0f
#define MAXM 16384
#define MAXK 1024
#define MAXN 4096

__device__ __half g_Xh[MAXM * MAXK];    // 32 MB scratch (permuted-k fp16)
__device__ __half g_Wh[MAXN * MAXK];    // 8 MB scratch (permuted-k fp16)

// ---- merged prep kernel (weff first, then x) -------------------------------
__global__ void prep_kernel(const float4* __restrict__ x, int n16x,
                            const float4* __restrict__ W,
                            const float4* __restrict__ gA,
                            const float*  __restrict__ gB,
                            const float4* __restrict__ lA,
                            const float*  __restrict__ lB,
                            int K16, int R, int n16w) {
    int idx = blockIdx.x * blockDim.x + threadIdx.x;
    if (idx < n16w) {
        // ---- Weff path ----
        int j = idx;
        int o = j / K16;
        int g = j - o * K16;
        int K4 = K16 * 4;
        float4 acc[4];
        #pragma unroll
        for (int q = 0; q < 4; q++) acc[q] = W[4 * j + q];
        for (int r = 0; r < R; r++) {
            float gb = gB[o * R + r] * LORA_SCALE;
            float lb = lB[o * R + r] * LORA_SCALE;
            #pragma unroll
            for (int q = 0; q < 4; q++) {
                float4 ga = gA[r * K4 + 4 * g + q];
                float4 la = lA[r * K4 + 4 * g + q];
                acc[q].x += gb * ga.x + lb * la.x;
                acc[q].y += gb * ga.y + lb * la.y;
                acc[q].z += gb * ga.z + lb * la.z;
                acc[q].w += gb * ga.w + lb * la.w;
            }
        }
        __half2 h[8];
        h[0] = __floats2half2_rn(acc[0].x, acc[0].y);
        h[1] = __floats2half2_rn(acc[2].x, acc[2].y);
        h[2] = __floats2half2_rn(acc[0].z, acc[0].w);
        h[3] = __floats2half2_rn(acc[2].z, acc[2].w);
        h[4] = __floats2half2_rn(acc[1].x, acc[1].y);
        h[5] = __floats2half2_rn(acc[3].x, acc[3].y);
        h[6] = __floats2half2_rn(acc[1].z, acc[1].w);
        h[7] = __floats2half2_rn(acc[3].z, acc[3].w);
        uint4* out = reinterpret_cast<uint4*>(g_Wh);
        const uint32_t* u = reinterpret_cast<const uint32_t*>(h);
        out[2 * j]     = make_uint4(u[0], u[1], u[2], u[3]);
        out[2 * j + 1] = make_uint4(u[4], u[5], u[6], u[7]);
        return;
    }
    int i = idx - n16w;
    if (i >= n16x) return;
    // ---- x path ----
    float4 a = x[4 * i + 0];
    float4 b = x[4 * i + 1];
    float4 c = x[4 * i + 2];
    float4 d = x[4 * i + 3];
    __half2 h[8];
    h[0] = __floats2half2_rn(a.x, a.y);
    h[1] = __floats2half2_rn(c.x, c.y);
    h[2] = __floats2half2_rn(a.z, a.w);
    h[3] = __floats2half2_rn(c.z, c.w);
    h[4] = __floats2half2_rn(b.x, b.y);
    h[5] = __floats2half2_rn(d.x, d.y);
    h[6] = __floats2half2_rn(b.z, b.w);
    h[7] = __floats2half2_rn(d.z, d.w);
    uint4* out = reinterpret_cast<uint4*>(g_Xh);
    const uint32_t* u = reinterpret_cast<const uint32_t*>(h);
    out[2 * i]     = make_uint4(u[0], u[1], u[2], u[3]);
    out[2 * i + 1] = make_uint4(u[4], u[5], u[6], u[7]);
}

// ---- GEMM ------------------------------------------------------------------
#define BM 128
#define BN 128
#define BK 64
#define NS 2
#define SSTH 80                          // halves per row slot (160 B stride)
#define ROWB 160u
#define A_H (BM * SSTH)                  // 10240 halves / stage
#define B_H (BN * SSTH)                  // 10240 halves / stage
#define STAGE_H (A_H + B_H)              // 20480 halves (40960 B)
#define GEMM_SMEM_BYTES (NS * STAGE_H * 2)   // 81920 B -> 2 CTAs/SM

__device__ __forceinline__ void cp16(uint32_t dst, const void* src) {
    asm volatile("cp.async.cg.shared.global [%0], [%1], 16;" :: "r"(dst), "l"(src));
}

__device__ __forceinline__ void mma16(float* c, const uint32_t* a, const uint32_t* b) {
    asm volatile(
        "mma.sync.aligned.m16n8k16.row.col.f32.f16.f16.f32 "
        "{%0,%1,%2,%3}, {%4,%5,%6,%7}, {%8,%9}, {%0,%1,%2,%3};"
        : "+f"(c[0]), "+f"(c[1]), "+f"(c[2]), "+f"(c[3])
        : "r"(a[0]), "r"(a[1]), "r"(a[2]), "r"(a[3]), "r"(b[0]), "r"(b[1]));
}

// issue cp.async group for K-tile kt into slot s (always commits a group)
__device__ __forceinline__ void issue_tile(const __half* Ag, const __half* Bg,
                                           int K, int KT, uint32_t a_base,
                                           int tid, int kt, int s) {
    if (kt < KT) {
        const int r0  = tid >> 3;            // 0..31
        const int ch  = tid & 7;             // 16B chunk within 128B of data
        const int kof = kt * BK + ch * 8;    // halves
        const uint32_t sb = a_base + (uint32_t)(s * STAGE_H) * 2u;
        #pragma unroll
        for (int i = 0; i < 4; i++) {        // A: 128 rows x 160B stride
            int row = r0 + 32 * i;
            cp16(sb + (uint32_t)row * ROWB + (uint32_t)ch * 16u,
                 Ag + (size_t)row * K + kof);
        }
        const uint32_t bb = sb + (uint32_t)A_H * 2u;
        #pragma unroll
        for (int i = 0; i < 4; i++) {        // B: 128 rows x 160B stride
            int row = r0 + 32 * i;
            cp16(bb + (uint32_t)row * ROWB + (uint32_t)ch * 16u,
                 Bg + (size_t)row * K + kof);
        }
    }
    asm volatile("cp.async.commit_group;" ::: "memory");
}

__global__ void __launch_bounds__(256, 2)
gemm_f16_kernel(const float* __restrict__ bias, float* __restrict__ C,
                int M, int N, int K) {
    extern __shared__ __half smem[];
    uint32_t a_base = (uint32_t)__cvta_generic_to_shared(smem);

    const int tid  = threadIdx.x;
    const int lane = tid & 31;
    const int warp = tid >> 5;
    const int wm   = warp & 1;        // 2 warps over M (64 rows each)
    const int wn   = warp >> 1;       // 4 warps over N (32 cols each)
    const int bm   = blockIdx.y * BM;
    const int bn   = blockIdx.x * BN;

    const __half* Ag = g_Xh + (size_t)bm * K;
    const __half* Bg = g_Wh + (size_t)bn * K;

    float c[4][4][4];
    #pragma unroll
    for (int mt = 0; mt < 4; mt++)
        #pragma unroll
        for (int nt = 0; nt < 4; nt++)
            #pragma unroll
            for (int r = 0; r < 4; r++)
                c[mt][nt][r] = 0.0f;

    const int KT = K / BK;            // 16

    issue_tile(Ag, Bg, K, KT, a_base, tid, 0, 0);

    const int t  = lane & 3;          // threadID in mma group
    const int gr = lane >> 2;         // groupID

    for (int kt = 0; kt < KT; kt++) {
        const int s = kt & 1;
        __syncthreads();                                  // done reading slot s^1
        issue_tile(Ag, Bg, K, KT, a_base, tid, kt + 1, s ^ 1);
        asm volatile("cp.async.wait_group %0;" :: "n"(1) : "memory");  // data(kt) ready
        __syncthreads();                                  // visibility across warps

        const __half* As = smem + s * STAGE_H;
        const __half* Bs = As + A_H;

        #pragma unroll
        for (int g = 0; g < 4; g++) {             // 4 x (k=16) steps
            const int kp = g * 16 + t * 4;        // halves
            uint32_t afr[4][4];
            uint32_t bfr[4][2];
            const int ar = wm * 64 + gr;
            #pragma unroll
            for (int mt = 0; mt < 4; mt++) {
                uint2 v0 = *reinterpret_cast<const uint2*>(As + (ar + mt * 16) * SSTH + kp);
                uint2 v1 = *reinterpret_cast<const uint2*>(As + (ar + mt * 16 + 8) * SSTH + kp);
                afr[mt][0] = v0.x;
                afr[mt][1] = v1.x;
                afr[mt][2] = v0.y;
                afr[mt][3] = v1.y;
            }
            const int br = wn * 32 + gr;
            #pragma unroll
            for (int nt = 0; nt < 4; nt++) {
                uint2 w = *reinterpret_cast<const uint2*>(Bs + (br + nt * 8) * SSTH + kp);
                bfr[nt][0] = w.x;
                bfr[nt][1] = w.y;
            }
            #pragma unroll
            for (int mt = 0; mt < 4; mt++)
                #pragma unroll
                for (int nt = 0; nt < 4; nt++)
                    mma16(c[mt][nt], afr[mt], bfr[nt]);
        }
    }

    // epilogue: += bias, store float2
    #pragma unroll
    for (int mt = 0; mt < 4; mt++) {
        int row0 = bm + wm * 64 + mt * 16 + gr;
        #pragma unroll
        for (int nt = 0; nt < 4; nt++) {
            int col = bn + wn * 32 + nt * 8 + t * 2;
            float2 bv = *reinterpret_cast<const float2*>(bias + col);
            float2 v0 = { c[mt][nt][0] + bv.x, c[mt][nt][1] + bv.y };
            float2 v1 = { c[mt][nt][2] + bv.x, c[mt][nt][3] + bv.y };
            *reinterpret_cast<float2*>(C + (size_t)row0 * N + col)       = v0;
            *reinterpret_cast<float2*>(C + (size_t)(row0 + 8) * N + col) = v1;
        }
    }
}

// ---- launch ----------------------------------------------------------------
extern "C" void kernel_launch(void* const* d_in, const int* in_sizes, int n_in,
                              void* d_out, int out_size) {
    (void)n_in; (void)out_size;
    const float* x  = (const float*)d_in[0];
    const float* W  = (const float*)d_in[1];
    const float* b  = (const float*)d_in[2];
    const float* gA = (const float*)d_in[3];
    const float* gB = (const float*)d_in[4];
    const float* lA = (const float*)d_in[5];
    const float* lB = (const float*)d_in[6];

    const int N = in_sizes[2];               // 4096
    const int K = in_sizes[1] / N;           // 1024
    const int R = in_sizes[4] / N;           // 8
    const int M = in_sizes[0] / K;           // 16384

    int n16x = (M * K) / 16;
    int K16  = K / 16;
    int n16w = N * K16;
    int blocks = (n16x + n16w + 255) / 256;
    prep_kernel<<<blocks, 256>>>((const float4*)x, n16x, (const float4*)W,
                                 (const float4*)gA, gB, (const float4*)lA, lB,
                                 K16, R, n16w);

    cudaFuncSetAttribute(gemm_f16_kernel,
                         cudaFuncAttributeMaxDynamicSharedMemorySize, GEMM_SMEM_BYTES);
    dim3 grid(N / BN, M / BM);               // (32, 128)
    gemm_f16_kernel<<<grid, 256, GEMM_SMEM_BYTES>>>(b, (float*)d_out, M, N, K);
}

// round 16
// speedup vs baseline: 1.3249x; 1.0412x over previous
#include <cuda_runtime.h>
#include <cuda_fp16.h>
#include <cstdint>
#include <cstddef>

// ----------------------------------------------------------------------------
// LoRALinear: out = x @ Weff^T + b, Weff = W + 2*(gB@gA + lB@lA)
//   k1 (merged): fold LoRA -> g_Wh (first), fp16-round x -> g_Xh, k-permuted
//       per 16: [k0,k1,k8,k9, k2,k3,k10,k11, k4,k5,k12,k13, k6,k7,k14,k15]
//   k2: mma.sync m16n8k16 f16 GEMM (fp32 accum), BM=128 BN=128 BK=64,
//       NS=3 cp.async ring, XOR-swizzled 128B rows (conflict-free, no pad),
//       ONE __syncthreads per K-iter, 2 CTAs/SM.
// ----------------------------------------------------------------------------

#define LORA_SCALE 2.0f
#define MAXM 16384
#define MAXK 1024
#define MAXN 4096

__device__ __half g_Xh[MAXM * MAXK];    // 32 MB scratch (permuted-k fp16)
__device__ __half g_Wh[MAXN * MAXK];    // 8 MB scratch (permuted-k fp16)

// ---- merged prep kernel (weff first, then x) -------------------------------
__global__ void prep_kernel(const float4* __restrict__ x, int n16x,
                            const float4* __restrict__ W,
                            const float4* __restrict__ gA,
                            const float*  __restrict__ gB,
                            const float4* __restrict__ lA,
                            const float*  __restrict__ lB,
                            int K16, int R, int n16w) {
    int idx = blockIdx.x * blockDim.x + threadIdx.x;
    if (idx < n16w) {
        int j = idx;
        int o = j / K16;
        int g = j - o * K16;
        int K4 = K16 * 4;
        float4 acc[4];
        #pragma unroll
        for (int q = 0; q < 4; q++) acc[q] = W[4 * j + q];
        for (int r = 0; r < R; r++) {
            float gb = gB[o * R + r] * LORA_SCALE;
            float lb = lB[o * R + r] * LORA_SCALE;
            #pragma unroll
            for (int q = 0; q < 4; q++) {
                float4 ga = gA[r * K4 + 4 * g + q];
                float4 la = lA[r * K4 + 4 * g + q];
                acc[q].x += gb * ga.x + lb * la.x;
                acc[q].y += gb * ga.y + lb * la.y;
                acc[q].z += gb * ga.z + lb * la.z;
                acc[q].w += gb * ga.w + lb * la.w;
            }
        }
        __half2 h[8];
        h[0] = __floats2half2_rn(acc[0].x, acc[0].y);
        h[1] = __floats2half2_rn(acc[2].x, acc[2].y);
        h[2] = __floats2half2_rn(acc[0].z, acc[0].w);
        h[3] = __floats2half2_rn(acc[2].z, acc[2].w);
        h[4] = __floats2half2_rn(acc[1].x, acc[1].y);
        h[5] = __floats2half2_rn(acc[3].x, acc[3].y);
        h[6] = __floats2half2_rn(acc[1].z, acc[1].w);
        h[7] = __floats2half2_rn(acc[3].z, acc[3].w);
        uint4* out = reinterpret_cast<uint4*>(g_Wh);
        const uint32_t* u = reinterpret_cast<const uint32_t*>(h);
        out[2 * j]     = make_uint4(u[0], u[1], u[2], u[3]);
        out[2 * j + 1] = make_uint4(u[4], u[5], u[6], u[7]);
        return;
    }
    int i = idx - n16w;
    if (i >= n16x) return;
    float4 a = x[4 * i + 0];
    float4 b = x[4 * i + 1];
    float4 c = x[4 * i + 2];
    float4 d = x[4 * i + 3];
    __half2 h[8];
    h[0] = __floats2half2_rn(a.x, a.y);
    h[1] = __floats2half2_rn(c.x, c.y);
    h[2] = __floats2half2_rn(a.z, a.w);
    h[3] = __floats2half2_rn(c.z, c.w);
    h[4] = __floats2half2_rn(b.x, b.y);
    h[5] = __floats2half2_rn(d.x, d.y);
    h[6] = __floats2half2_rn(b.z, b.w);
    h[7] = __floats2half2_rn(d.z, d.w);
    uint4* out = reinterpret_cast<uint4*>(g_Xh);
    const uint32_t* u = reinterpret_cast<const uint32_t*>(h);
    out[2 * i]     = make_uint4(u[0], u[1], u[2], u[3]);
    out[2 * i + 1] = make_uint4(u[4], u[5], u[6], u[7]);
}

// ---- GEMM ------------------------------------------------------------------
#define BM 128
#define BN 128
#define BK 64
#define NS 3
// rows are 128 B (64 halves), no padding; 16B-chunk XOR swizzle:
//   chunk' = chunk ^ ((row & 3) << 1)
#define A_H (BM * 64)                    // 8192 halves / stage
#define B_H (BN * 64)                    // 8192 halves / stage
#define STAGE_H (A_H + B_H)              // 16384 halves (32768 B)
#define GEMM_SMEM_BYTES (NS * STAGE_H * 2)   // 98304 B -> 2 CTAs/SM

__device__ __forceinline__ void cp16(uint32_t dst, const void* src) {
    asm volatile("cp.async.cg.shared.global [%0], [%1], 16;" :: "r"(dst), "l"(src));
}

__device__ __forceinline__ void mma16(float* c, const uint32_t* a, const uint32_t* b) {
    asm volatile(
        "mma.sync.aligned.m16n8k16.row.col.f32.f16.f16.f32 "
        "{%0,%1,%2,%3}, {%4,%5,%6,%7}, {%8,%9}, {%0,%1,%2,%3};"
        : "+f"(c[0]), "+f"(c[1]), "+f"(c[2]), "+f"(c[3])
        : "r"(a[0]), "r"(a[1]), "r"(a[2]), "r"(a[3]), "r"(b[0]), "r"(b[1]));
}

// issue cp.async group for K-tile kt into slot s (always commits a group)
__device__ __forceinline__ void issue_tile(const __half* Ag, const __half* Bg,
                                           int K, int KT, uint32_t a_base,
                                           int tid, int kt, int s) {
    if (kt < KT) {
        const int r0  = tid >> 3;            // 0..31
        const int ch  = tid & 7;             // 16B chunk in row
        const int chs = ch ^ ((r0 & 3) << 1);   // swizzled chunk (lane-const)
        const int kof = kt * BK + ch * 8;    // halves in gmem (linear)
        const uint32_t sb = a_base + (uint32_t)(s * STAGE_H) * 2u;
        #pragma unroll
        for (int i = 0; i < 4; i++) {        // A: 128 rows x 128B
            int row = r0 + 32 * i;           // row&3 == r0&3
            cp16(sb + (uint32_t)(row * 128 + chs * 16),
                 Ag + (size_t)row * K + kof);
        }
        const uint32_t bb = sb + (uint32_t)A_H * 2u;
        #pragma unroll
        for (int i = 0; i < 4; i++) {        // B: 128 rows x 128B
            int row = r0 + 32 * i;
            cp16(bb + (uint32_t)(row * 128 + chs * 16),
                 Bg + (size_t)row * K + kof);
        }
    }
    asm volatile("cp.async.commit_group;" ::: "memory");
}

__global__ void __launch_bounds__(256, 2)
gemm_f16_kernel(const float* __restrict__ bias, float* __restrict__ C,
                int M, int N, int K) {
    extern __shared__ __half smem[];
    uint32_t a_base = (uint32_t)__cvta_generic_to_shared(smem);

    const int tid  = threadIdx.x;
    const int lane = tid & 31;
    const int warp = tid >> 5;
    const int wm   = warp & 1;        // 2 warps over M (64 rows each)
    const int wn   = warp >> 1;       // 4 warps over N (32 cols each)
    const int bm   = blockIdx.y * BM;
    const int bn   = blockIdx.x * BN;

    const __half* Ag = g_Xh + (size_t)bm * K;
    const __half* Bg = g_Wh + (size_t)bn * K;

    float c[4][4][4];
    #pragma unroll
    for (int mt = 0; mt < 4; mt++)
        #pragma unroll
        for (int nt = 0; nt < 4; nt++)
            #pragma unroll
            for (int r = 0; r < 4; r++)
                c[mt][nt][r] = 0.0f;

    const int KT = K / BK;            // 16

    issue_tile(Ag, Bg, K, KT, a_base, tid, 0, 0);
    issue_tile(Ag, Bg, K, KT, a_base, tid, 1, 1);

    const int t  = lane & 3;          // threadID in mma group
    const int gr = lane >> 2;         // groupID (= fragment row offset)
    const int sw = (gr & 3) << 1;     // thread-constant chunk swizzle

    int slot = 0;                     // slot of tile kt
    for (int kt = 0; kt < KT; kt++) {
        asm volatile("cp.async.wait_group %0;" :: "n"(1) : "memory");  // tile kt ready
        __syncthreads();              // visibility + all warps done with slot (kt-1)%NS
        {
            int ns = slot + 2; if (ns >= NS) ns -= NS;   // (kt+2)%NS == (kt-1)%NS
            issue_tile(Ag, Bg, K, KT, a_base, tid, kt + 2, ns);
        }

        const __half* As = smem + slot * STAGE_H;
        const __half* Bs = As + A_H;

        #pragma unroll
        for (int g = 0; g < 4; g++) {             // 4 x (k=16) steps
            // swizzled in-row offset (halves): chunk (2g + t/2) ^ sw, sub (t&1)*4
            const int kp = (((2 * g + (t >> 1)) ^ sw) << 3) + (t & 1) * 4;
            uint32_t afr[4][4];
            uint32_t bfr[4][2];
            const int ar = wm * 64 + gr;
            #pragma unroll
            for (int mt = 0; mt < 4; mt++) {
                uint2 v0 = *reinterpret_cast<const uint2*>(As + (ar + mt * 16) * 64 + kp);
                uint2 v1 = *reinterpret_cast<const uint2*>(As + (ar + mt * 16 + 8) * 64 + kp);
                afr[mt][0] = v0.x;
                afr[mt][1] = v1.x;
                afr[mt][2] = v0.y;
                afr[mt][3] = v1.y;
            }
            const int br = wn * 32 + gr;
            #pragma unroll
            for (int nt = 0; nt < 4; nt++) {
                uint2 w = *reinterpret_cast<const uint2*>(Bs + (br + nt * 8) * 64 + kp);
                bfr[nt][0] = w.x;
                bfr[nt][1] = w.y;
            }
            #pragma unroll
            for (int mt = 0; mt < 4; mt++)
                #pragma unroll
                for (int nt = 0; nt < 4; nt++)
                    mma16(c[mt][nt], afr[mt], bfr[nt]);
        }
        if (++slot == NS) slot = 0;
    }

    // epilogue: += bias, store float2
    #pragma unroll
    for (int mt = 0; mt < 4; mt++) {
        int row0 = bm + wm * 64 + mt * 16 + gr;
        #pragma unroll
        for (int nt = 0; nt < 4; nt++) {
            int col = bn + wn * 32 + nt * 8 + t * 2;
            float2 bv = *reinterpret_cast<const float2*>(bias + col);
            float2 v0 = { c[mt][nt][0] + bv.x, c[mt][nt][1] + bv.y };
            float2 v1 = { c[mt][nt][2] + bv.x, c[mt][nt][3] + bv.y };
            *reinterpret_cast<float2*>(C + (size_t)row0 * N + col)       = v0;
            *reinterpret_cast<float2*>(C + (size_t)(row0 + 8) * N + col) = v1;
        }
    }
}

// ---- launch ----------------------------------------------------------------
extern "C" void kernel_launch(void* const* d_in, const int* in_sizes, int n_in,
                              void* d_out, int out_size) {
    (void)n_in; (void)out_size;
    const float* x  = (const float*)d_in[0];
    const float* W  = (const float*)d_in[1];
    const float* b  = (const float*)d_in[2];
    const float* gA = (const float*)d_in[3];
    const float* gB = (const float*)d_in[4];
    const float* lA = (const float*)d_in[5];
    const float* lB = (const float*)d_in[6];

    const int N = in_sizes[2];               // 4096
    const int K = in_sizes[1] / N;           // 1024
    const int R = in_sizes[4] / N;           // 8
    const int M = in_sizes[0] / K;           // 16384

    int n16x = (M * K) / 16;
    int K16  = K / 16;
    int n16w = N * K16;
    int blocks = (n16x + n16w + 255) / 256;
    prep_kernel<<<blocks, 256>>>((const float4*)x, n16x, (const float4*)W,
                                 (const float4*)gA, gB, (const float4*)lA, lB,
                                 K16, R, n16w);

    cudaFuncSetAttribute(gemm_f16_kernel,
                         cudaFuncAttributeMaxDynamicSharedMemorySize, GEMM_SMEM_BYTES);
    dim3 grid(N / BN, M / BM);               // (32, 128)
    gemm_f16_kernel<<<grid, 256, GEMM_SMEM_BYTES>>>(b, (float*)d_out, M, N, K);
}

// round 17
// speedup vs baseline: 1.4359x; 1.0838x over previous
#include <cuda_runtime.h>
#include <cuda_fp16.h>
#include <cstdint>
#include <cstddef>

// ----------------------------------------------------------------------------
// LoRALinear: out = x @ Weff^T + b, Weff = W + 2*(gB@gA + lB@lA)
//   k1 (merged): fold LoRA -> g_Wh (first), fp16-round x -> g_Xh (k-LINEAR)
//   k2: mma.sync m16n8k16 f16 GEMM (fp32 accum), BM=128 BN=128 BK=64,
//       NS=3 cp.async ring, ldmatrix.x4 fragment loads,
//       XOR swizzle chunk^(row&7) on 128B rows, 1 sync/iter, 2 CTAs/SM.
// ----------------------------------------------------------------------------

#define LORA_SCALE 2.0f
#define MAXM 16384
#define MAXK 1024
#define MAXN 4096

__device__ __half g_Xh[MAXM * MAXK];    // 32 MB scratch (fp16, linear k)
__device__ __half g_Wh[MAXN * MAXK];    // 8 MB scratch (fp16, linear k)

// ---- merged prep kernel (weff first, then x), linear layout ----------------
__global__ void prep_kernel(const float4* __restrict__ x, int n16x,
                            const float4* __restrict__ W,
                            const float4* __restrict__ gA,
                            const float*  __restrict__ gB,
                            const float4* __restrict__ lA,
                            const float*  __restrict__ lB,
                            int K16, int R, int n16w) {
    int idx = blockIdx.x * blockDim.x + threadIdx.x;
    if (idx < n16w) {
        int j = idx;
        int o = j / K16;
        int g = j - o * K16;
        int K4 = K16 * 4;
        float4 acc[4];
        #pragma unroll
        for (int q = 0; q < 4; q++) acc[q] = W[4 * j + q];
        for (int r = 0; r < R; r++) {
            float gb = gB[o * R + r] * LORA_SCALE;
            float lb = lB[o * R + r] * LORA_SCALE;
            #pragma unroll
            for (int q = 0; q < 4; q++) {
                float4 ga = gA[r * K4 + 4 * g + q];
                float4 la = lA[r * K4 + 4 * g + q];
                acc[q].x += gb * ga.x + lb * la.x;
                acc[q].y += gb * ga.y + lb * la.y;
                acc[q].z += gb * ga.z + lb * la.z;
                acc[q].w += gb * ga.w + lb * la.w;
            }
        }
        __half2 h[8];
        #pragma unroll
        for (int q = 0; q < 4; q++) {
            h[2 * q]     = __floats2half2_rn(acc[q].x, acc[q].y);
            h[2 * q + 1] = __floats2half2_rn(acc[q].z, acc[q].w);
        }
        uint4* out = reinterpret_cast<uint4*>(g_Wh);
        const uint32_t* u = reinterpret_cast<const uint32_t*>(h);
        out[2 * j]     = make_uint4(u[0], u[1], u[2], u[3]);
        out[2 * j + 1] = make_uint4(u[4], u[5], u[6], u[7]);
        return;
    }
    int i = idx - n16w;
    if (i >= n16x) return;
    float4 v[4];
    #pragma unroll
    for (int q = 0; q < 4; q++) v[q] = x[4 * i + q];
    __half2 h[8];
    #pragma unroll
    for (int q = 0; q < 4; q++) {
        h[2 * q]     = __floats2half2_rn(v[q].x, v[q].y);
        h[2 * q + 1] = __floats2half2_rn(v[q].z, v[q].w);
    }
    uint4* out = reinterpret_cast<uint4*>(g_Xh);
    const uint32_t* u = reinterpret_cast<const uint32_t*>(h);
    out[2 * i]     = make_uint4(u[0], u[1], u[2], u[3]);
    out[2 * i + 1] = make_uint4(u[4], u[5], u[6], u[7]);
}

// ---- GEMM ------------------------------------------------------------------
#define BM 128
#define BN 128
#define BK 64
#define NS 3
// rows are 128 B (64 halves), no padding; 16B-chunk XOR swizzle:
//   chunk' = chunk ^ (row & 7)
#define A_BYT (BM * 128)                 // 16384 B / stage
#define B_BYT (BN * 128)                 // 16384 B / stage
#define STAGE_BYT (A_BYT + B_BYT)        // 32768 B
#define GEMM_SMEM_BYTES (NS * STAGE_BYT) // 98304 B -> 2 CTAs/SM

__device__ __forceinline__ void cp16(uint32_t dst, const void* src) {
    asm volatile("cp.async.cg.shared.global [%0], [%1], 16;" :: "r"(dst), "l"(src));
}

__device__ __forceinline__ void mma16(float* c, const uint32_t* a, const uint32_t* b) {
    asm volatile(
        "mma.sync.aligned.m16n8k16.row.col.f32.f16.f16.f32 "
        "{%0,%1,%2,%3}, {%4,%5,%6,%7}, {%8,%9}, {%0,%1,%2,%3};"
        : "+f"(c[0]), "+f"(c[1]), "+f"(c[2]), "+f"(c[3])
        : "r"(a[0]), "r"(a[1]), "r"(a[2]), "r"(a[3]), "r"(b[0]), "r"(b[1]));
}

__device__ __forceinline__ void ldsm4(uint32_t& r0, uint32_t& r1,
                                      uint32_t& r2, uint32_t& r3, uint32_t addr) {
    asm volatile("ldmatrix.sync.aligned.m8n8.x4.shared.b16 {%0,%1,%2,%3}, [%4];"
                 : "=r"(r0), "=r"(r1), "=r"(r2), "=r"(r3) : "r"(addr));
}

// issue cp.async group for K-tile kt into slot s (always commits a group)
__device__ __forceinline__ void issue_tile(const __half* Ag, const __half* Bg,
                                           int K, int KT, uint32_t a_base,
                                           int tid, int kt, int s) {
    if (kt < KT) {
        const int r0  = tid >> 3;               // 0..31
        const int ch  = tid & 7;                // 16B chunk in row
        const int chs = ch ^ (r0 & 7);          // swizzled chunk (lane-const)
        const int kof = kt * BK + ch * 8;       // halves (linear k)
        const uint32_t sb = a_base + (uint32_t)(s * STAGE_BYT);
        #pragma unroll
        for (int i = 0; i < 4; i++) {           // A: 128 rows x 128B
            int row = r0 + 32 * i;              // row&7 == r0&7
            cp16(sb + (uint32_t)(row * 128 + chs * 16),
                 Ag + (size_t)row * K + kof);
        }
        const uint32_t bb = sb + (uint32_t)A_BYT;
        #pragma unroll
        for (int i = 0; i < 4; i++) {           // B: 128 rows x 128B
            int row = r0 + 32 * i;
            cp16(bb + (uint32_t)(row * 128 + chs * 16),
                 Bg + (size_t)row * K + kof);
        }
    }
    asm volatile("cp.async.commit_group;" ::: "memory");
}

__global__ void __launch_bounds__(256, 2)
gemm_f16_kernel(const float* __restrict__ bias, float* __restrict__ C,
                int M, int N, int K) {
    extern __shared__ __half smem[];
    uint32_t a_base = (uint32_t)__cvta_generic_to_shared(smem);

    const int tid  = threadIdx.x;
    const int lane = tid & 31;
    const int warp = tid >> 5;
    const int wm   = warp & 1;        // 2 warps over M (64 rows each)
    const int wn   = warp >> 1;       // 4 warps over N (32 cols each)
    const int bm   = blockIdx.y * BM;
    const int bn   = blockIdx.x * BN;

    const __half* Ag = g_Xh + (size_t)bm * K;
    const __half* Bg = g_Wh + (size_t)bn * K;

    float c[4][4][4];
    #pragma unroll
    for (int mt = 0; mt < 4; mt++)
        #pragma unroll
        for (int nt = 0; nt < 4; nt++)
            #pragma unroll
            for (int r = 0; r < 4; r++)
                c[mt][nt][r] = 0.0f;

    const int KT = K / BK;            // 16

    issue_tile(Ag, Bg, K, KT, a_base, tid, 0, 0);
    issue_tile(Ag, Bg, K, KT, a_base, tid, 1, 1);

    const int t  = lane & 3;          // threadID in mma group
    const int gr = lane >> 2;         // groupID
    const uint32_t swz = (uint32_t)(lane & 7);   // per-lane swizzle key

    // per-lane ldmatrix row offsets (bytes within A / B regions)
    // A x4 tile: lanes 0-15 -> rows 0-15 (klo), lanes 16-31 -> rows 0-15 (khi)
    const uint32_t arow  = (uint32_t)(wm * 64 + (lane & 15));
    const uint32_t kbA   = (uint32_t)(lane >> 4);           // 0=klo, 1=khi
    // B x4 tile pair: lanes 0-7 n0-7 klo, 8-15 n0-7 khi, 16-23 n8-15 klo, 24-31 khi
    const uint32_t brow  = (uint32_t)(wn * 32 + (lane & 7) + ((lane >> 4) & 1) * 8);
    const uint32_t kbB   = (uint32_t)((lane >> 3) & 1);

    int slot = 0;                     // slot of tile kt
    for (int kt = 0; kt < KT; kt++) {
        asm volatile("cp.async.wait_group %0;" :: "n"(1) : "memory");  // tile kt ready
        __syncthreads();              // all warps done with slot (kt-1)%NS
        {
            int ns = slot + 2; if (ns >= NS) ns -= NS;   // (kt+2)%NS == (kt-1)%NS
            issue_tile(Ag, Bg, K, KT, a_base, tid, kt + 2, ns);
        }

        const uint32_t As = a_base + (uint32_t)(slot * STAGE_BYT);
        const uint32_t Bs = As + (uint32_t)A_BYT;
        const uint32_t aRow = As + arow * 128u;
        const uint32_t bRow = Bs + brow * 128u;

        #pragma unroll
        for (int g = 0; g < 4; g++) {             // 4 x (k=16) steps
            const uint32_t cA = (((2u * g + kbA) ^ swz) << 4);
            const uint32_t cB = (((2u * g + kbB) ^ swz) << 4);
            uint32_t afr[4][4];
            uint32_t bfr[4][2];
            #pragma unroll
            for (int mt = 0; mt < 4; mt++)
                ldsm4(afr[mt][0], afr[mt][1], afr[mt][2], afr[mt][3],
                      aRow + (uint32_t)(mt * 16 * 128) + cA);
            #pragma unroll
            for (int p = 0; p < 2; p++)
                ldsm4(bfr[2 * p][0], bfr[2 * p][1], bfr[2 * p + 1][0], bfr[2 * p + 1][1],
                      bRow + (uint32_t)(p * 16 * 128) + cB);
            #pragma unroll
            for (int mt = 0; mt < 4; mt++)
                #pragma unroll
                for (int nt = 0; nt < 4; nt++)
                    mma16(c[mt][nt], afr[mt], bfr[nt]);
        }
        if (++slot == NS) slot = 0;
    }

    // epilogue: += bias, store float2
    #pragma unroll
    for (int mt = 0; mt < 4; mt++) {
        int row0 = bm + wm * 64 + mt * 16 + gr;
        #pragma unroll
        for (int nt = 0; nt < 4; nt++) {
            int col = bn + wn * 32 + nt * 8 + t * 2;
            float2 bv = *reinterpret_cast<const float2*>(bias + col);
            float2 v0 = { c[mt][nt][0] + bv.x, c[mt][nt][1] + bv.y };
            float2 v1 = { c[mt][nt][2] + bv.x, c[mt][nt][3] + bv.y };
            *reinterpret_cast<float2*>(C + (size_t)row0 * N + col)       = v0;
            *reinterpret_cast<float2*>(C + (size_t)(row0 + 8) * N + col) = v1;
        }
    }
}

// ---- launch ----------------------------------------------------------------
extern "C" void kernel_launch(void* const* d_in, const int* in_sizes, int n_in,
                              void* d_out, int out_size) {
    (void)n_in; (void)out_size;
    const float* x  = (const float*)d_in[0];
    const float* W  = (const float*)d_in[1];
    const float* b  = (const float*)d_in[2];
    const float* gA = (const float*)d_in[3];
    const float* gB = (const float*)d_in[4];
    const float* lA = (const float*)d_in[5];
    const float* lB = (const float*)d_in[6];

    const int N = in_sizes[2];               // 4096
    const int K = in_sizes[1] / N;           // 1024
    const int R = in_sizes[4] / N;           // 8
    const int M = in_sizes[0] / K;           // 16384

    int n16x = (M * K) / 16;
    int K16  = K / 16;
    int n16w = N * K16;
    int blocks = (n16x + n16w + 255) / 256;
    prep_kernel<<<blocks, 256>>>((const float4*)x, n16x, (const float4*)W,
                                 (const float4*)gA, gB, (const float4*)lA, lB,
                                 K16, R, n16w);

    cudaFuncSetAttribute(gemm_f16_kernel,
                         cudaFuncAttributeMaxDynamicSharedMemorySize, GEMM_SMEM_BYTES);
    dim3 grid(N / BN, M / BM);               // (32, 128)
    gemm_f16_kernel<<<grid, 256, GEMM_SMEM_BYTES>>>(b, (float*)d_out, M, N, K);
}